// round 9
// baseline (speedup 1.0000x reference)
#include <cuda_runtime.h>

#define CNUM 19
#define HWD (512*512)
#define BATCH 8
#define NPIX (BATCH*HWD)
#define NP4 (NPIX/4)                 // 524,288 float4 groups
#define CH4 (HWD/4)                  // 65,536 = 2^16
#define NBINS (CNUM*CNUM)            // 361
#define INP_ELEMS (BATCH*CNUM*HWD)   // 39,845,888

#define NBLOCKS (148*7)              // exactly-resident single wave @ 7 CTAs/SM

__global__ void zero_out_kernel(float* __restrict__ out)
{
    int i = blockIdx.x * blockDim.x + threadIdx.x;
    if (i < NBINS) out[i] = 0.0f;
}

__global__ void __launch_bounds__(256, 7)
confmat_kernel(const float* __restrict__ inp,
               const int*   __restrict__ tgt,
               float*       __restrict__ out)
{
    __shared__ int hist[NBINS];
    for (int i = threadIdx.x; i < NBINS; i += blockDim.x) hist[i] = 0;
    __syncthreads();

    const int stride = gridDim.x * blockDim.x;          // 1036*256 = 265,216
    for (int p4 = blockIdx.x * blockDim.x + threadIdx.x; p4 < NP4; p4 += stride) {
        const int b   = p4 >> 16;          // p4 / CH4
        const int hw4 = p4 & (CH4 - 1);    // p4 % CH4
        const float4* base = reinterpret_cast<const float4*>(inp)
                             + (long long)b * (CNUM * CH4) + hw4;

        float4 m = __ldg(&base[0]);
        int ax = 0, ay = 0, az = 0, aw = 0;
        #pragma unroll
        for (int c = 1; c < CNUM; c++) {
            float4 v = __ldg(&base[c * CH4]);
            if (v.x > m.x) { m.x = v.x; ax = c; }
            if (v.y > m.y) { m.y = v.y; ay = c; }
            if (v.z > m.z) { m.z = v.z; az = c; }
            if (v.w > m.w) { m.w = v.w; aw = c; }
        }

        const int4 t = __ldg(reinterpret_cast<const int4*>(tgt) + p4);
        int i0 = t.x * CNUM + ax;  i0 = min(max(i0, 0), NBINS - 1);
        int i1 = t.y * CNUM + ay;  i1 = min(max(i1, 0), NBINS - 1);
        int i2 = t.z * CNUM + az;  i2 = min(max(i2, 0), NBINS - 1);
        int i3 = t.w * CNUM + aw;  i3 = min(max(i3, 0), NBINS - 1);
        atomicAdd(&hist[i0], 1);
        atomicAdd(&hist[i1], 1);
        atomicAdd(&hist[i2], 1);
        atomicAdd(&hist[i3], 1);
    }
    __syncthreads();

    for (int i = threadIdx.x; i < NBINS; i += blockDim.x) {
        const int v = hist[i];
        if (v) atomicAdd(&out[i], (float)v);
    }
}

extern "C" void kernel_launch(void* const* d_in, const int* in_sizes, int n_in,
                              void* d_out, int out_size)
{
    const float* inp = nullptr;
    const int*   tgt = nullptr;
    for (int i = 0; i < n_in; i++) {
        const long long s = in_sizes[i];
        if (s == (long long)INP_ELEMS || s == (long long)INP_ELEMS * 4)
            inp = (const float*)d_in[i];
        else if (s == (long long)NPIX || s == (long long)NPIX * 4)
            tgt = (const int*)d_in[i];
    }
    if (!inp || !tgt) {
        int i_big = -1, i_second = -1;
        for (int i = 0; i < n_in; i++)
            if (i_big < 0 || in_sizes[i] > in_sizes[i_big]) i_big = i;
        for (int i = 0; i < n_in; i++) {
            if (i == i_big || in_sizes[i] <= 16) continue;
            if (i_second < 0 || in_sizes[i] > in_sizes[i_second]) i_second = i;
        }
        if (!inp && i_big >= 0)    inp = (const float*)d_in[i_big];
        if (!tgt && i_second >= 0) tgt = (const int*)d_in[i_second];
        if (!inp && n_in > 0) inp = (const float*)d_in[0];
        if (!tgt && n_in > 1) tgt = (const int*)d_in[1];
    }

    float* out = (float*)d_out;
    (void)out_size;

    zero_out_kernel<<<2, 256>>>(out);
    if (inp && tgt) {
        confmat_kernel<<<NBLOCKS, 256>>>(inp, tgt, out);   // 1036 blocks, 1 wave
    }
}

// round 10
// speedup vs baseline: 1.0717x; 1.0717x over previous
#include <cuda_runtime.h>

#define CNUM 19
#define HWD (512*512)
#define NPIX (8*HWD)
#define NP4 (NPIX/4)                 // 524,288 float4 groups
#define CH4 (HWD/4)                  // 65,536 = 2^16
#define NBINS (CNUM*CNUM)            // 361
#define INP_ELEMS (8*CNUM*HWD)       // 39,845,888
#define NBLOCKS 592                  // best-measured config (4 CTAs/SM, 1 wave)

// Monotonic accumulators — NEVER reset (graph-replay safe).
__device__ unsigned long long g_tot[NBINS];
__device__ unsigned long long g_prev[NBINS];
__device__ unsigned int       g_ticket;

__global__ void __launch_bounds__(256)
confmat_kernel(const float* __restrict__ inp,
               const int*   __restrict__ tgt,
               float*       __restrict__ out)
{
    __shared__ int hist[NBINS];
    for (int i = threadIdx.x; i < NBINS; i += blockDim.x) hist[i] = 0;
    __syncthreads();

    const int stride = gridDim.x * blockDim.x;
    for (int p4 = blockIdx.x * blockDim.x + threadIdx.x; p4 < NP4; p4 += stride) {
        const int b   = p4 >> 16;          // p4 / CH4
        const int hw4 = p4 & (CH4 - 1);    // p4 % CH4
        const float4* base = reinterpret_cast<const float4*>(inp)
                             + (long long)b * (CNUM * CH4) + hw4;

        float4 m = __ldg(&base[0]);
        int ax = 0, ay = 0, az = 0, aw = 0;
        #pragma unroll
        for (int c = 1; c < CNUM; c++) {
            float4 v = __ldg(&base[c * CH4]);
            if (v.x > m.x) { m.x = v.x; ax = c; }
            if (v.y > m.y) { m.y = v.y; ay = c; }
            if (v.z > m.z) { m.z = v.z; az = c; }
            if (v.w > m.w) { m.w = v.w; aw = c; }
        }

        const int4 t = __ldg(reinterpret_cast<const int4*>(tgt) + p4);
        int i0 = t.x * CNUM + ax;  i0 = min(max(i0, 0), NBINS - 1);
        int i1 = t.y * CNUM + ay;  i1 = min(max(i1, 0), NBINS - 1);
        int i2 = t.z * CNUM + az;  i2 = min(max(i2, 0), NBINS - 1);
        int i3 = t.w * CNUM + aw;  i3 = min(max(i3, 0), NBINS - 1);
        atomicAdd(&hist[i0], 1);
        atomicAdd(&hist[i1], 1);
        atomicAdd(&hist[i2], 1);
        atomicAdd(&hist[i3], 1);
    }
    __syncthreads();

    // Flush per-block histogram into the monotonic global accumulator.
    for (int i = threadIdx.x; i < NBINS; i += blockDim.x) {
        const int v = hist[i];
        if (v) atomicAdd(&g_tot[i], (unsigned long long)v);
    }

    // Last-block-of-this-launch writes the per-launch delta to out.
    __shared__ unsigned int s_ticket;
    __threadfence();                       // make g_tot adds visible
    __syncthreads();                       // all threads of block done flushing
    if (threadIdx.x == 0)
        s_ticket = atomicAdd(&g_ticket, 1u);
    __syncthreads();

    if ((s_ticket % NBLOCKS) == (NBLOCKS - 1)) {
        __threadfence();                   // acquire: see all blocks' g_tot adds
        for (int i = threadIdx.x; i < NBINS; i += blockDim.x) {
            const unsigned long long t = g_tot[i];
            const unsigned long long d = t - g_prev[i];
            g_prev[i] = t;
            out[i] = (float)(unsigned int)d;   // counts < 2^24, exact in f32
        }
    }
}

extern "C" void kernel_launch(void* const* d_in, const int* in_sizes, int n_in,
                              void* d_out, int out_size)
{
    const float* inp = nullptr;
    const int*   tgt = nullptr;
    for (int i = 0; i < n_in; i++) {
        const long long s = in_sizes[i];
        if (s == (long long)INP_ELEMS || s == (long long)INP_ELEMS * 4)
            inp = (const float*)d_in[i];
        else if (s == (long long)NPIX || s == (long long)NPIX * 4)
            tgt = (const int*)d_in[i];
    }
    if (!inp || !tgt) {
        int i_big = -1, i_second = -1;
        for (int i = 0; i < n_in; i++)
            if (i_big < 0 || in_sizes[i] > in_sizes[i_big]) i_big = i;
        for (int i = 0; i < n_in; i++) {
            if (i == i_big || in_sizes[i] <= 16) continue;
            if (i_second < 0 || in_sizes[i] > in_sizes[i_second]) i_second = i;
        }
        if (!inp && i_big >= 0)    inp = (const float*)d_in[i_big];
        if (!tgt && i_second >= 0) tgt = (const int*)d_in[i_second];
        if (!inp && n_in > 0) inp = (const float*)d_in[0];
        if (!tgt && n_in > 1) tgt = (const int*)d_in[1];
    }

    float* out = (float*)d_out;
    (void)out_size;

    if (inp && tgt) {
        confmat_kernel<<<NBLOCKS, 256>>>(inp, tgt, out);   // single kernel node
    }
}

// round 11
// speedup vs baseline: 1.1460x; 1.0693x over previous
#include <cuda_runtime.h>

#define CNUM 19
#define HWD (512*512)
#define NPIX (8*HWD)
#define NP4 (NPIX/4)                 // 524,288 float4 groups
#define CH4 (HWD/4)                  // 65,536 = 2^16
#define NBINS (CNUM*CNUM)            // 361
#define INP_ELEMS (8*CNUM*HWD)       // 39,845,888
#define NBLOCKS (148*3)              // 444: 3 CTAs/SM, single wave

__global__ void zero_out_kernel(float* __restrict__ out)
{
    int i = blockIdx.x * blockDim.x + threadIdx.x;
    if (i < NBINS) out[i] = 0.0f;
}

__global__ void __launch_bounds__(256, 3)   // allow up to 84 regs -> deep load batching
confmat_kernel(const float* __restrict__ inp,
               const int*   __restrict__ tgt,
               float*       __restrict__ out)
{
    __shared__ int hist[NBINS];
    for (int i = threadIdx.x; i < NBINS; i += blockDim.x) hist[i] = 0;
    __syncthreads();

    const int stride = gridDim.x * blockDim.x;
    for (int p4 = blockIdx.x * blockDim.x + threadIdx.x; p4 < NP4; p4 += stride) {
        const int b   = p4 >> 16;          // p4 / CH4
        const int hw4 = p4 & (CH4 - 1);    // p4 % CH4
        const float4* base = reinterpret_cast<const float4*>(inp)
                             + (long long)b * (CNUM * CH4) + hw4;

        // Two independent argmax chains (c = 0..9 and c = 10..18) so the
        // compiler can front-batch loads for both and halve the serial
        // compare/select dependency depth. Merge keeps first-max semantics.
        float4 m0 = __ldg(&base[0]);
        int a0x = 0, a0y = 0, a0z = 0, a0w = 0;
        #pragma unroll
        for (int c = 1; c < 10; c++) {
            float4 v = __ldg(&base[c * CH4]);
            if (v.x > m0.x) { m0.x = v.x; a0x = c; }
            if (v.y > m0.y) { m0.y = v.y; a0y = c; }
            if (v.z > m0.z) { m0.z = v.z; a0z = c; }
            if (v.w > m0.w) { m0.w = v.w; a0w = c; }
        }

        float4 m1 = __ldg(&base[10 * CH4]);
        int a1x = 10, a1y = 10, a1z = 10, a1w = 10;
        #pragma unroll
        for (int c = 11; c < CNUM; c++) {
            float4 v = __ldg(&base[c * CH4]);
            if (v.x > m1.x) { m1.x = v.x; a1x = c; }
            if (v.y > m1.y) { m1.y = v.y; a1y = c; }
            if (v.z > m1.z) { m1.z = v.z; a1z = c; }
            if (v.w > m1.w) { m1.w = v.w; a1w = c; }
        }

        // Merge: strict > keeps the lower-index (first) max, matching jnp.argmax.
        const int ax = (m1.x > m0.x) ? a1x : a0x;
        const int ay = (m1.y > m0.y) ? a1y : a0y;
        const int az = (m1.z > m0.z) ? a1z : a0z;
        const int aw = (m1.w > m0.w) ? a1w : a0w;

        const int4 t = __ldg(reinterpret_cast<const int4*>(tgt) + p4);
        int i0 = t.x * CNUM + ax;  i0 = min(max(i0, 0), NBINS - 1);
        int i1 = t.y * CNUM + ay;  i1 = min(max(i1, 0), NBINS - 1);
        int i2 = t.z * CNUM + az;  i2 = min(max(i2, 0), NBINS - 1);
        int i3 = t.w * CNUM + aw;  i3 = min(max(i3, 0), NBINS - 1);
        atomicAdd(&hist[i0], 1);
        atomicAdd(&hist[i1], 1);
        atomicAdd(&hist[i2], 1);
        atomicAdd(&hist[i3], 1);
    }
    __syncthreads();

    for (int i = threadIdx.x; i < NBINS; i += blockDim.x) {
        const int v = hist[i];
        if (v) atomicAdd(&out[i], (float)v);
    }
}

extern "C" void kernel_launch(void* const* d_in, const int* in_sizes, int n_in,
                              void* d_out, int out_size)
{
    const float* inp = nullptr;
    const int*   tgt = nullptr;
    for (int i = 0; i < n_in; i++) {
        const long long s = in_sizes[i];
        if (s == (long long)INP_ELEMS || s == (long long)INP_ELEMS * 4)
            inp = (const float*)d_in[i];
        else if (s == (long long)NPIX || s == (long long)NPIX * 4)
            tgt = (const int*)d_in[i];
    }
    if (!inp || !tgt) {
        int i_big = -1, i_second = -1;
        for (int i = 0; i < n_in; i++)
            if (i_big < 0 || in_sizes[i] > in_sizes[i_big]) i_big = i;
        for (int i = 0; i < n_in; i++) {
            if (i == i_big || in_sizes[i] <= 16) continue;
            if (i_second < 0 || in_sizes[i] > in_sizes[i_second]) i_second = i;
        }
        if (!inp && i_big >= 0)    inp = (const float*)d_in[i_big];
        if (!tgt && i_second >= 0) tgt = (const int*)d_in[i_second];
        if (!inp && n_in > 0) inp = (const float*)d_in[0];
        if (!tgt && n_in > 1) tgt = (const int*)d_in[1];
    }

    float* out = (float*)d_out;
    (void)out_size;

    zero_out_kernel<<<2, 256>>>(out);
    if (inp && tgt) {
        confmat_kernel<<<NBLOCKS, 256>>>(inp, tgt, out);
    }
}

// round 12
// speedup vs baseline: 1.1843x; 1.0334x over previous
#include <cuda_runtime.h>

#define CNUM 19
#define HWD (512*512)
#define NPIX (8*HWD)
#define NP4 (NPIX/4)                 // 524,288 float4 groups
#define CH4 (HWD/4)                  // 65,536 = 2^16
#define NBINS (CNUM*CNUM)            // 361
#define INP_ELEMS (8*CNUM*HWD)       // 39,845,888
#define NBLOCKS 592                  // best-measured: 4 CTAs/SM, single wave

__global__ void zero_out_kernel(float* __restrict__ out)
{
    int i = blockIdx.x * blockDim.x + threadIdx.x;
    if (i < NBINS) out[i] = 0.0f;
}

__global__ void __launch_bounds__(256)
confmat_kernel(const float* __restrict__ inp,
               const int*   __restrict__ tgt,
               float*       __restrict__ out)
{
    __shared__ int hist[NBINS];
    for (int i = threadIdx.x; i < NBINS; i += blockDim.x) hist[i] = 0;
    __syncthreads();

    const int stride = gridDim.x * blockDim.x;
    for (int p4 = blockIdx.x * blockDim.x + threadIdx.x; p4 < NP4; p4 += stride) {
        const int b   = p4 >> 16;          // p4 / CH4
        const int hw4 = p4 & (CH4 - 1);    // p4 % CH4
        const float4* base = reinterpret_cast<const float4*>(inp)
                             + (long long)b * (CNUM * CH4) + hw4;

        // Hoist target load into the front batch (independent of the argmax chain).
        const int4 t = __ldcs(reinterpret_cast<const int4*>(tgt) + p4);

        // Streaming loads: data touched exactly once -> evict-first.
        float4 m = __ldcs(&base[0]);
        int ax = 0, ay = 0, az = 0, aw = 0;
        #pragma unroll
        for (int c = 1; c < CNUM; c++) {
            float4 v = __ldcs(&base[c * CH4]);
            if (v.x > m.x) { m.x = v.x; ax = c; }
            if (v.y > m.y) { m.y = v.y; ay = c; }
            if (v.z > m.z) { m.z = v.z; az = c; }
            if (v.w > m.w) { m.w = v.w; aw = c; }
        }

        int i0 = t.x * CNUM + ax;  i0 = min(max(i0, 0), NBINS - 1);
        int i1 = t.y * CNUM + ay;  i1 = min(max(i1, 0), NBINS - 1);
        int i2 = t.z * CNUM + az;  i2 = min(max(i2, 0), NBINS - 1);
        int i3 = t.w * CNUM + aw;  i3 = min(max(i3, 0), NBINS - 1);
        atomicAdd(&hist[i0], 1);
        atomicAdd(&hist[i1], 1);
        atomicAdd(&hist[i2], 1);
        atomicAdd(&hist[i3], 1);
    }
    __syncthreads();

    for (int i = threadIdx.x; i < NBINS; i += blockDim.x) {
        const int v = hist[i];
        if (v) atomicAdd(&out[i], (float)v);
    }
}

extern "C" void kernel_launch(void* const* d_in, const int* in_sizes, int n_in,
                              void* d_out, int out_size)
{
    const float* inp = nullptr;
    const int*   tgt = nullptr;
    for (int i = 0; i < n_in; i++) {
        const long long s = in_sizes[i];
        if (s == (long long)INP_ELEMS || s == (long long)INP_ELEMS * 4)
            inp = (const float*)d_in[i];
        else if (s == (long long)NPIX || s == (long long)NPIX * 4)
            tgt = (const int*)d_in[i];
    }
    if (!inp || !tgt) {
        int i_big = -1, i_second = -1;
        for (int i = 0; i < n_in; i++)
            if (i_big < 0 || in_sizes[i] > in_sizes[i_big]) i_big = i;
        for (int i = 0; i < n_in; i++) {
            if (i == i_big || in_sizes[i] <= 16) continue;
            if (i_second < 0 || in_sizes[i] > in_sizes[i_second]) i_second = i;
        }
        if (!inp && i_big >= 0)    inp = (const float*)d_in[i_big];
        if (!tgt && i_second >= 0) tgt = (const int*)d_in[i_second];
        if (!inp && n_in > 0) inp = (const float*)d_in[0];
        if (!tgt && n_in > 1) tgt = (const int*)d_in[1];
    }

    float* out = (float*)d_out;
    (void)out_size;

    zero_out_kernel<<<2, 256>>>(out);
    if (inp && tgt) {
        confmat_kernel<<<NBLOCKS, 256>>>(inp, tgt, out);
    }
}